// round 13
// baseline (speedup 1.0000x reference)
#include <cuda_runtime.h>
#include <cuda_bf16.h>
#include <math.h>

typedef unsigned long long ull;
typedef unsigned int uint;

#define BATCH  128
#define TSTEPS 256
#define NBLK   128
#define NTHR   512

#define CELL_SLOTS 6291456u            // 384 tiles * 16384 uint4 slots
#define FC_SLOTS   524288u             // 128 tiles * 4096
#define TOT_SLOTS  (CELL_SLOTS + FC_SLOTS)

// dynamic smem map (bytes):
// [0, 73728)         two A buffers (hi plane 4608 uints + lo plane 4608 uints each)
// [73728, 122880)    THREE B buffers, 16 KB each (cp.async staged weight chunks)
// [122880, 156672)   zs[128][66] floats (also final-phase scratch)
#define PL_U     4608                  // 128*36 uints per plane
#define ABUF_U   9216                  // uints per A buffer (hi+lo)
#define BSM_OFF  73728
#define ZS_OFF   122880
#define SMEM_BYTES 156672

// ---------------- device scratch -------------------------------------------
__device__ float g_P[2][1024][4096];           // emb @ W_ih(l0)^T, fp32
__device__ uint  g_hx[2][2][2][BATCH * 1024];  // packed (hi,lo) bf16 h
__device__ float g_c[2][2][BATCH * 1024];
__device__ uint  g_whx[BATCH * 2048];          // packed scrambled fc input
__device__ float g_logitsP[8][BATCH * 1024];   // split-K partials
__device__ int   g_feed[BATCH];
__device__ int   g_ended[BATCH];
__device__ unsigned g_cnt = 0, g_gen = 0;
__device__ uint4 g_WB[TOT_SLOTS];              // pre-fragmented split-bf16 weights

// ---------------- helpers ----------------------------------------------------
__device__ __forceinline__ uint prmt(uint a, uint b, uint s) {
    uint r; asm("prmt.b32 %0, %1, %2, %3;" : "=r"(r) : "r"(a), "r"(b), "r"(s));
    return r;
}
__device__ __forceinline__ uint b2u(__nv_bfloat162 v) { return *reinterpret_cast<uint*>(&v); }
__device__ __forceinline__ uint pack_split(float v) {
    __nv_bfloat16 h = __float2bfloat16_rn(v);
    float hf = __bfloat162float(h);
    __nv_bfloat16 l = __float2bfloat16_rn(v - hf);
    return (uint)__bfloat16_as_ushort(h) | ((uint)__bfloat16_as_ushort(l) << 16);
}
__device__ __forceinline__ float sigf(float x) { return 1.0f / (1.0f + expf(-x)); }
__device__ __forceinline__ uint s2u(const void* p) {
    uint a;
    asm("{ .reg .u64 t; cvta.to.shared.u64 t, %1; cvt.u32.u64 %0, t; }" : "=r"(a) : "l"(p));
    return a;
}

#define MMA_OP(d, a, bb0, bb1) \
    asm volatile( \
        "mma.sync.aligned.m16n8k16.row.col.f32.bf16.bf16.f32 " \
        "{%0,%1,%2,%3}, {%4,%5,%6,%7}, {%8,%9}, {%0,%1,%2,%3};" \
        : "+f"((d)[0]), "+f"((d)[1]), "+f"((d)[2]), "+f"((d)[3]) \
        : "r"((a)[0]), "r"((a)[1]), "r"((a)[2]), "r"((a)[3]), "r"(bb0), "r"(bb1))

#define CP_ASYNC16(daddr, saddr) \
    asm volatile("cp.async.cg.shared.global [%0], [%1], 16;" :: "r"(daddr), "l"(saddr) : "memory")
#define CP_COMMIT() asm volatile("cp.async.commit_group;" ::: "memory")
#define CP_WAIT1()  asm volatile("cp.async.wait_group 1;" ::: "memory")
#define CP_WAIT0()  asm volatile("cp.async.wait_group 0;" ::: "memory")

// ---------------- f32x2 helpers (pcomp only) --------------------------------
__device__ __forceinline__ ull pk2(float lo, float hi) {
    ull r; asm("mov.b64 %0, {%1,%2};" : "=l"(r) : "f"(lo), "f"(hi)); return r;
}
__device__ __forceinline__ void fma2(ull& d, ull a, ull b) {
    asm("fma.rn.f32x2 %0, %1, %2, %0;" : "+l"(d) : "l"(a), "l"(b));
}
__device__ __forceinline__ float2 unpk(ull v) {
    float2 r; asm("mov.b64 {%0,%1}, %2;" : "=f"(r.x), "=f"(r.y) : "l"(v)); return r;
}

// ---------------- software grid barrier --------------------------------------
__device__ __forceinline__ void gbar() {
    __threadfence();
    __syncthreads();
    if (threadIdx.x == 0) {
        unsigned gen = atomicAdd(&g_gen, 0u);
        unsigned arrived = atomicAdd(&g_cnt, 1u);
        if (arrived == NBLK - 1u) {
            atomicExch(&g_cnt, 0u);
            __threadfence();
            atomicAdd(&g_gen, 1u);
        } else {
            while (atomicAdd(&g_gen, 0u) == gen) { __nanosleep(64); }
        }
        __threadfence();
    }
    __syncthreads();
}

// ---------------- init --------------------------------------------------------
__device__ __forceinline__ void init_phase(int bid, const int* __restrict__ yy,
                                           const float* __restrict__ h_t,
                                           const float* __restrict__ h_tr,
                                           const float* __restrict__ c0,
                                           const float* __restrict__ c0r) {
    const int tid = threadIdx.x;
    const int LBH = BATCH * 1024;
    for (int i = bid * NTHR + tid; i < 2 * LBH; i += NBLK * NTHR) {
        int l = i / LBH, r = i % LBH, j = r & 1023;
        g_hx[l][0][0][r] = pack_split(h_t[l * LBH + r]);
        g_hx[l][1][0][r] = pack_split(h_tr[l * LBH + r]);
        g_c[l][0][r] = c0[l * 1024 + j];
        g_c[l][1][r] = c0r[l * 1024 + j];
    }
    if (bid == 0 && tid < BATCH) {
        g_feed[tid] = yy[tid * TSTEPS];
        g_ended[tid] = 0;
    }
}

// ---------------- setup: split + pre-fragment weights ------------------------
__device__ void setup_weights(int bid,
    const float* __restrict__ W_ih, const float* __restrict__ W_hh,
    const float* __restrict__ W_ihr, const float* __restrict__ W_hhr,
    const float* __restrict__ fcW) {
    for (uint s = bid * NTHR + threadIdx.x; s < TOT_SLOTS; s += NBLK * NTHR) {
        const float* p;
        if (s < CELL_SLOTS) {
            uint tile = s >> 14, rem = s & 16383u;
            uint ks = rem >> 8, nf = (rem >> 5) & 7, lane = rem & 31;
            uint dir = tile / 192, seg = (tile / 64) % 3, jt = tile & 63;
            const float* W;
            if (seg == 0)      W = dir ? W_hhr : W_hh;
            else if (seg == 1) W = (dir ? W_ihr : W_ih) + (size_t)4096 * 1024;
            else               W = (dir ? W_hhr : W_hh) + (size_t)4096 * 1024;
            uint n = nf * 8 + (lane >> 2);
            uint row = (n >> 4) * 1024 + jt * 16 + (n & 15);
            uint kb = ks * 16 + (lane & 3) * 2;
            p = W + (size_t)row * 1024 + kb;
        } else {
            uint srel = s - CELL_SLOTS;
            uint f = srel >> 12, rem = srel & 4095u;
            uint ks = rem >> 8, nf = (rem >> 5) & 7, lane = rem & 31;
            uint et = f >> 3, ks2 = f & 7;
            uint n = nf * 8 + (lane >> 2);
            uint row = et * 64 + n;
            uint kb = ks2 * 256 + ks * 16 + (lane & 3) * 2;
            p = fcW + (size_t)row * 2048 + kb;
        }
        float2 r01 = __ldg((const float2*)p);
        float2 r89 = __ldg((const float2*)(p + 8));
        __nv_bfloat162 H01 = __floats2bfloat162_rn(r01.x, r01.y);
        __nv_bfloat162 H89 = __floats2bfloat162_rn(r89.x, r89.y);
        __nv_bfloat162 L01 = __floats2bfloat162_rn(r01.x - __bfloat162float(H01.x),
                                                   r01.y - __bfloat162float(H01.y));
        __nv_bfloat162 L89 = __floats2bfloat162_rn(r89.x - __bfloat162float(H89.x),
                                                   r89.y - __bfloat162float(H89.y));
        g_WB[s] = make_uint4(b2u(H01), b2u(H89), b2u(L01), b2u(L89));
    }
}

// ---------------- pcomp (fp32 f32x2, 512 thr): P = emb @ W_ih(l0)^T ----------
__device__ void pcomp_phase(char* dsm, int bid, const float* __restrict__ emb,
                            const float* __restrict__ W_ih,
                            const float* __restrict__ W_ihr) {
    float (*As)[16][132] = (float(*)[16][132])(dsm);
    float (*Bs)[16][68]  = (float(*)[16][68])(dsm + 2 * 16 * 132 * 4);
    const int tid = threadIdx.x;
    const int ty = tid >> 4, tx = tid & 15;
    const int m0 = ty << 2, n0 = tx << 2;
    const int ar = tid >> 2, q4 = (tid & 3) << 2;
    const bool bload = (tid < 256);
    const int br = tid >> 2;   // 0..63 when bload

    for (int it = 0; it < 8; ++it) {
        int tile = bid + (it << 7);
        int dir = tile >> 9, mt = (tile >> 6) & 7, nt = tile & 63;
        const float* Bw = dir ? W_ihr : W_ih;
        const int m0g = mt << 7, n0g = nt << 6;
        const float* arow = emb + (size_t)(m0g + ar) * 1024 + q4;
        const float* brow = Bw + (size_t)(n0g + br) * 1024 + q4;

        ull acc[2][4];
#pragma unroll
        for (int i = 0; i < 2; i++)
#pragma unroll
            for (int j = 0; j < 4; j++) acc[i][j] = 0ULL;

        float4 pa = __ldg((const float4*)arow);
        float4 pb = make_float4(0.f, 0.f, 0.f, 0.f);
        if (bload) pb = __ldg((const float4*)brow);
        int cur = 0;
        {
            float (*A)[132] = As[0]; float (*B)[68] = Bs[0];
            A[q4+0][ar]=pa.x; A[q4+1][ar]=pa.y; A[q4+2][ar]=pa.z; A[q4+3][ar]=pa.w;
            if (bload) { B[q4+0][br]=pb.x; B[q4+1][br]=pb.y; B[q4+2][br]=pb.z; B[q4+3][br]=pb.w; }
        }
        __syncthreads();
        for (int kk = 0; kk < 64; ++kk) {
            const bool more = (kk + 1) < 64;
            if (more) {
                int k0 = (kk + 1) << 4;
                pa = __ldg((const float4*)(arow + k0));
                if (bload) pb = __ldg((const float4*)(brow + k0));
            }
            {
                const float (*A)[132] = As[cur]; const float (*B)[68] = Bs[cur];
#pragma unroll
                for (int k = 0; k < 16; k++) {
                    const ull* ap = (const ull*)&A[k][m0];
                    ull a0 = ap[0], a1 = ap[1];
                    float4 bv = *(const float4*)&B[k][n0];
                    ull p0=pk2(bv.x,bv.x), p1=pk2(bv.y,bv.y), p2=pk2(bv.z,bv.z), p3=pk2(bv.w,bv.w);
                    fma2(acc[0][0],a0,p0); fma2(acc[0][1],a0,p1); fma2(acc[0][2],a0,p2); fma2(acc[0][3],a0,p3);
                    fma2(acc[1][0],a1,p0); fma2(acc[1][1],a1,p1); fma2(acc[1][2],a1,p2); fma2(acc[1][3],a1,p3);
                }
            }
            if (more) {
                float (*A)[132] = As[cur^1]; float (*B)[68] = Bs[cur^1];
                A[q4+0][ar]=pa.x; A[q4+1][ar]=pa.y; A[q4+2][ar]=pa.z; A[q4+3][ar]=pa.w;
                if (bload) { B[q4+0][br]=pb.x; B[q4+1][br]=pb.y; B[q4+2][br]=pb.z; B[q4+3][br]=pb.w; }
                __syncthreads();
                cur ^= 1;
            }
        }
        __syncthreads();
#pragma unroll
        for (int mp = 0; mp < 2; mp++) {
            int m = m0g + m0 + (mp << 1);
#pragma unroll
            for (int j = 0; j < 4; j++) {
                float2 v = unpk(acc[mp][j]);
                g_P[dir][m][n0g + n0 + j] = v.x;
                g_P[dir][m + 1][n0g + n0 + j] = v.y;
            }
        }
        __syncthreads();
    }
}

// ---------------- HMMA GEMM core (race-free triple-buffered B stream) --------
// zs[128][66] = A[128, K] @ W^T tile (64 n); A packed (hi,lo) uints;
// warp tile 16m x 32n; B chunks (16 KB) TRIPLE-buffered via cp.async issued
// strictly after __syncthreads (no writer/reader overlap); MMAs product-major
// (dependency distance 4 per accumulator).
__device__ __noinline__ void gemm_mma(uint* smA, uint smb, float (*zs)[66],
    const uint* __restrict__ Ax0, const uint* __restrict__ Ax1,
    int astride, int koff, int nch, int nch0,
    const uint4* __restrict__ tb0, const uint4* __restrict__ tb1) {
    const int tid = threadIdx.x;
    const int lane = tid & 31, wid = tid >> 5;
    const int wn = wid & 1, wm = wid >> 1;
    const int lq = lane >> 2, lr = lane & 3;
    const int ar = tid >> 2, aq = tid & 3;
    uint4* smB = (uint4*)((char*)smA + BSM_OFF);
    const uint smbB = smb + BSM_OFF;

    float acc[4][4];
#pragma unroll
    for (int f = 0; f < 4; f++)
#pragma unroll
        for (int k = 0; k < 4; k++) acc[f][k] = 0.0f;

    // ---- prologue: A0 -> Abuf0, B0 -> Bbuf0, B1 -> Bbuf1, av <- A1
    {
        const uint* s = Ax0 + (size_t)ar * astride + koff + aq * 16;
        uint* dh = smA + ar * 36 + aq * 8;
        uint* dl = dh + PL_U;
#pragma unroll
        for (int i = 0; i < 4; i++) {
            uint4 v = __ldcg((const uint4*)(s + i * 4));
            *(uint2*)(dh + i * 2) = make_uint2(prmt(v.x, v.y, 0x5410), prmt(v.z, v.w, 0x5410));
            *(uint2*)(dl + i * 2) = make_uint2(prmt(v.x, v.y, 0x7632), prmt(v.z, v.w, 0x7632));
        }
    }
    {
        const uint4* s = tb0 + tid;         // chunk 0 always from tb0 (nch0 >= 1)
        uint d = smbB + tid * 16;
        CP_ASYNC16(d, s);
        CP_ASYNC16(d + 8192, s + 512);
        CP_COMMIT();
    }
    uint4 av[4];
    if (nch > 1) {
        int sg = (1 >= nch0);
        const uint4* s = (sg ? tb1 : tb0) + (size_t)(1 - (sg ? nch0 : 0)) * 1024 + tid;
        uint d = smbB + 16384 + tid * 16;
        CP_ASYNC16(d, s);
        CP_ASYNC16(d + 8192, s + 512);
        CP_COMMIT();
        const uint* as = (sg ? Ax1 : Ax0) + (size_t)ar * astride + koff
                         + (1 - (sg ? nch0 : 0)) * 64 + aq * 16;
#pragma unroll
        for (int i = 0; i < 4; i++) av[i] = __ldcg((const uint4*)(as + i * 4));
    }

    for (int c = 0; c < nch; ++c) {
        // wait for B(c): keep at most 1 newer group (B(c+1)) in flight
        if (c + 1 < nch) CP_WAIT1(); else CP_WAIT0();
        __syncthreads();   // B(c) + A(c) visible; Bbuf[(c+2)%3] & Abuf[(c+1)&1] free

        if (c + 2 < nch) { // issue B(c+2) into the buffer last read at chunk c-1
            int cn = c + 2;
            int sg = (cn >= nch0);
            const uint4* s = (sg ? tb1 : tb0) + (size_t)(cn - (sg ? nch0 : 0)) * 1024 + tid;
            uint d = smbB + ((cn % 3) * 16384) + tid * 16;
            CP_ASYNC16(d, s);
            CP_ASYNC16(d + 8192, s + 512);
            CP_COMMIT();
        }
        if (c + 1 < nch) { // stage A(c+1) from regs; prefetch A(c+2)
            uint* dh = smA + ((c + 1) & 1) * ABUF_U + ar * 36 + aq * 8;
            uint* dl = dh + PL_U;
#pragma unroll
            for (int i = 0; i < 4; i++) {
                *(uint2*)(dh + i * 2) = make_uint2(prmt(av[i].x, av[i].y, 0x5410),
                                                   prmt(av[i].z, av[i].w, 0x5410));
                *(uint2*)(dl + i * 2) = make_uint2(prmt(av[i].x, av[i].y, 0x7632),
                                                   prmt(av[i].z, av[i].w, 0x7632));
            }
            if (c + 2 < nch) {
                int cn = c + 2;
                int sg = (cn >= nch0);
                const uint* s = (sg ? Ax1 : Ax0) + (size_t)ar * astride + koff
                                + (cn - (sg ? nch0 : 0)) * 64 + aq * 16;
#pragma unroll
                for (int i = 0; i < 4; i++) av[i] = __ldcg((const uint4*)(s + i * 4));
            }
        }

        // ---- compute chunk c
        const uint* Ah = smA + (c & 1) * ABUF_U;
        const uint* Al = Ah + PL_U;
        const uint4* Bb = smB + (c % 3) * 1024;
#pragma unroll
        for (int kl = 0; kl < 4; kl++) {
            const uint4* bp = Bb + (kl * 8 + wn * 4) * 32 + lane;
            uint4 B0 = bp[0], B1 = bp[32], B2 = bp[64], B3 = bp[96];
            const int colh = kl * 8 + lr;
            const int m = wm * 16 + lq;
            uint ah[4], al[4];
            ah[0] = Ah[m * 36 + colh];     ah[1] = Ah[(m + 8) * 36 + colh];
            ah[2] = Ah[m * 36 + colh + 4]; ah[3] = Ah[(m + 8) * 36 + colh + 4];
            al[0] = Al[m * 36 + colh];     al[1] = Al[(m + 8) * 36 + colh];
            al[2] = Al[m * 36 + colh + 4]; al[3] = Al[(m + 8) * 36 + colh + 4];
            // product-major: per-acc order stays hh, hl, lh (bitwise as before),
            // but RAW distance per accumulator is 4 instead of 1.
            MMA_OP(acc[0], ah, B0.x, B0.y); MMA_OP(acc[1], ah, B1.x, B1.y);
            MMA_OP(acc[2], ah, B2.x, B2.y); MMA_OP(acc[3], ah, B3.x, B3.y);
            MMA_OP(acc[0], ah, B0.z, B0.w); MMA_OP(acc[1], ah, B1.z, B1.w);
            MMA_OP(acc[2], ah, B2.z, B2.w); MMA_OP(acc[3], ah, B3.z, B3.w);
            MMA_OP(acc[0], al, B0.x, B0.y); MMA_OP(acc[1], al, B1.x, B1.y);
            MMA_OP(acc[2], al, B2.x, B2.y); MMA_OP(acc[3], al, B3.x, B3.y);
        }
    }

    // accumulators -> zs
#pragma unroll
    for (int f = 0; f < 4; f++) {
        int m = wm * 16 + lq;
        int n = wn * 32 + f * 8 + lr * 2;
        *(float2*)&zs[m][n]     = make_float2(acc[f][0], acc[f][1]);
        *(float2*)&zs[m + 8][n] = make_float2(acc[f][2], acc[f][3]);
    }
    __syncthreads();
}

// ---------------- epilogues ---------------------------------------------------
__device__ __forceinline__ void cell_epilogue(float (*zs)[66], int layer, int dir,
    int j0, int np, const float* __restrict__ bi, const float* __restrict__ bh) {
    const int tid = threadIdx.x;
#pragma unroll
    for (int it = 0; it < 4; ++it) {
        int pidx = tid + it * NTHR;
        int b = pidx >> 4, jj = pidx & 15;
        int jg = j0 + jj;
        float zi = zs[b][jj]      + bi[jg]        + bh[jg];
        float zf = zs[b][16 + jj] + bi[1024 + jg] + bh[1024 + jg];
        float zg = zs[b][32 + jj] + bi[2048 + jg] + bh[2048 + jg];
        float zo = zs[b][48 + jj] + bi[3072 + jg] + bh[3072 + jg];
        if (layer == 0) {
            int feed = __ldcg(&g_feed[b]);
            const float* pr = &g_P[dir][feed][0];
            zi += pr[jg]; zf += pr[1024 + jg]; zg += pr[2048 + jg]; zo += pr[3072 + jg];
        }
        float ig = sigf(zi), fg = sigf(zf), gv = tanhf(zg), og = sigf(zo);
        int idx = b * 1024 + jg;
        float cnew = fg * g_c[layer][dir][idx] + ig * gv;
        float hnew = og * tanhf(cnew);
        g_c[layer][dir][idx] = cnew;
        uint hp = pack_split(hnew);
        g_hx[layer][dir][np][idx] = hp;
        if (layer == 1) {
            int cc = (dir << 10) + jg;  // wh[cc>>4][(cc&15)*128 + b]
            g_whx[((cc >> 4) << 11) + ((cc & 15) << 7) + b] = hp;
        }
    }
}

__device__ __forceinline__ void fc_epilogue(float (*zs)[66], int et, int ks2) {
    const int tid = threadIdx.x;
    const int b = tid >> 2, n0 = (tid & 3) << 4;
    float* lp = &g_logitsP[ks2][b * 1024 + et * 64 + n0];
#pragma unroll
    for (int j = 0; j < 16; j++) lp[j] = zs[b][n0 + j];
}

// ---------------- final phase --------------------------------------------------
__device__ __forceinline__ void final_phase(char* dsm, int bid,
                                            const float* __restrict__ fc_b,
                                            float* __restrict__ out, int t) {
    const int b = bid;
    const int tid = threadIdx.x;
    float* sl = (float*)(dsm + ZS_OFF);
    float* sv = sl + 1024;
    int*   si = (int*)(sl + 1536);
    float* ssum = sl + 2048;

    const int end = __ldcg(&g_ended[b]);
    float bv = -3.402823466e38f;
    int bidx = 0;
    for (int e = tid; e < 1024; e += NTHR) {
        float v;
        if (end) {
            v = (e == 1) ? 1.0f : 0.0f;
        } else {
            v = fc_b[e];
#pragma unroll
            for (int s = 0; s < 8; s++) v += __ldcg(&g_logitsP[s][b * 1024 + e]);
        }
        sl[e] = v;
        if (v > bv) { bv = v; bidx = e; }
    }
    sv[tid] = bv; si[tid] = bidx;
    __syncthreads();
    for (int s = NTHR / 2; s > 0; s >>= 1) {
        if (tid < s) {
            float v2 = sv[tid + s]; int i2 = si[tid + s];
            if (v2 > sv[tid] || (v2 == sv[tid] && i2 < si[tid])) { sv[tid] = v2; si[tid] = i2; }
        }
        __syncthreads();
    }
    float mx = sv[0];
    int label = si[0];
    __syncthreads();

    float ps = 0.0f;
    for (int e = tid; e < 1024; e += NTHR) ps += expf(sl[e] - mx);
    ssum[tid] = ps;
    __syncthreads();
    for (int s = NTHR / 2; s > 0; s >>= 1) {
        if (tid < s) ssum[tid] += ssum[tid + s];
        __syncthreads();
    }
    float inv = 1.0f / ssum[0];

    float* orow = out + ((size_t)b * TSTEPS + t) * 1024;
    for (int e = tid; e < 1024; e += NTHR) orow[e] = expf(sl[e] - mx) * inv;

    if (tid == 0) {
        g_feed[b] = label;
        g_ended[b] = end | (label == 1);  // EOS = 1
    }
}

// ---------------- mega kernel --------------------------------------------------
__global__ void __launch_bounds__(NTHR, 1) main_kernel(
    const int* __restrict__ yy,
    const float* __restrict__ h_t, const float* __restrict__ h_tr,
    const float* __restrict__ c0, const float* __restrict__ c0r,
    const float* __restrict__ emb,
    const float* __restrict__ W_ih, const float* __restrict__ W_hh,
    const float* __restrict__ b_ih, const float* __restrict__ b_hh,
    const float* __restrict__ W_ihr, const float* __restrict__ W_hhr,
    const float* __restrict__ b_ihr, const float* __restrict__ b_hhr,
    const float* __restrict__ fcW, const float* __restrict__ fc_b,
    float* __restrict__ out) {
    extern __shared__ char dsm[];
    uint* smA = (uint*)dsm;
    const uint smb = s2u(dsm);
    float (*zs)[66] = (float(*)[66])(dsm + ZS_OFF);
    const int bid = blockIdx.x;

    init_phase(bid, yy, h_t, h_tr, c0, c0r);
    setup_weights(bid, W_ih, W_hh, W_ihr, W_hhr, fcW);
    pcomp_phase(dsm, bid, emb, W_ih, W_ihr);
    gbar();

    const int dir = bid >> 6;
    const int jt = bid & 63;
    const int j0 = jt << 4;
    const int et = bid >> 3;
    const int ks2 = bid & 7;
    const float* bi0 = (dir ? b_ihr : b_ih);
    const float* bh0 = (dir ? b_hhr : b_hh);
    const float* bi1 = bi0 + 4096;
    const float* bh1 = bh0 + 4096;
    const uint4* tL0  = g_WB + (size_t)((dir * 3 + 0) * 64 + jt) * 16384;
    const uint4* tL1a = g_WB + (size_t)((dir * 3 + 1) * 64 + jt) * 16384;
    const uint4* tL1b = g_WB + (size_t)((dir * 3 + 2) * 64 + jt) * 16384;
    const uint4* tFC  = g_WB + CELL_SLOTS + (size_t)(et * 8 + ks2) * 4096;

    for (int t = 0; t < TSTEPS; ++t) {
        const int p = t & 1;
        const int np = p ^ 1;
        // layer 0: z = h0_prev @ Whh0^T (+ P[feed] in epilogue)
        gemm_mma(smA, smb, zs, g_hx[0][dir][p], g_hx[0][dir][p], 1024, 0, 16, 16, tL0, tL0);
        cell_epilogue(zs, 0, dir, j0, np, bi0, bh0);
        gbar();
        // layer 1: z = h0_new @ Wih1^T + h1_prev @ Whh1^T
        gemm_mma(smA, smb, zs, g_hx[0][dir][np], g_hx[1][dir][p], 1024, 0, 32, 16, tL1a, tL1b);
        cell_epilogue(zs, 1, dir, j0, np, bi1, bh1);
        gbar();
        // fc: logits partial, K slice ks2*256..+256
        gemm_mma(smA, smb, zs, g_whx, g_whx, 2048, ks2 * 256, 4, 4, tFC, tFC);
        fc_epilogue(zs, et, ks2);
        gbar();
        final_phase(dsm, bid, fc_b, out, t);
        gbar();
    }
}

// ---------------- launch --------------------------------------------------------
extern "C" void kernel_launch(void* const* d_in, const int* in_sizes, int n_in,
                              void* d_out, int out_size) {
    const int* yy = (const int*)d_in[0];
    const float* h_t = (const float*)d_in[1];
    const float* h_tr = (const float*)d_in[2];
    // d_in[3] = x_lens (unused by the reference computation)
    const float* emb = (const float*)d_in[4];
    const float* W_ih = (const float*)d_in[5];
    const float* W_hh = (const float*)d_in[6];
    const float* b_ih = (const float*)d_in[7];
    const float* b_hh = (const float*)d_in[8];
    const float* W_ihr = (const float*)d_in[9];
    const float* W_hhr = (const float*)d_in[10];
    const float* b_ihr = (const float*)d_in[11];
    const float* b_hhr = (const float*)d_in[12];
    const float* c0 = (const float*)d_in[13];
    const float* c0r = (const float*)d_in[14];
    const float* fc_W = (const float*)d_in[15];
    const float* fc_b = (const float*)d_in[16];
    float* out = (float*)d_out;

    cudaFuncSetAttribute(main_kernel, cudaFuncAttributeMaxDynamicSharedMemorySize, SMEM_BYTES);
    main_kernel<<<NBLK, NTHR, SMEM_BYTES>>>(yy, h_t, h_tr, c0, c0r, emb,
                                            W_ih, W_hh, b_ih, b_hh,
                                            W_ihr, W_hhr, b_ihr, b_hhr,
                                            fc_W, fc_b, out);
}

// round 14
// speedup vs baseline: 1.4772x; 1.4772x over previous
#include <cuda_runtime.h>
#include <cuda_bf16.h>
#include <math.h>

typedef unsigned long long ull;
typedef unsigned int uint;

#define BATCH  128
#define TSTEPS 256
#define NBLK   128
#define NTHR   512

#define CELL_SLOTS 6291456u            // 384 tiles * 16384 uint4 slots
#define FC_SLOTS   524288u             // 128 tiles * 4096
#define TOT_SLOTS  (CELL_SLOTS + FC_SLOTS)

// dynamic smem map (bytes):
// [0, 65536)        FOUR B buffers, 16 KB each (cp.async weight chunks)
// [65536, 99328)    zs[128][66] floats (also final-phase scratch)
// [99328, 107776)   hs[16][132] uints (epilogue wh pair-exchange)
#define ZS_OFF   65536
#define HS_OFF   99328
#define SMEM_BYTES 107776

// ---------------- device scratch -------------------------------------------
__device__ float g_P[2][1024][4096];            // emb @ W_ih(l0)^T, fp32
__device__ float g_c[2][2][BATCH * 1024];
__device__ float g_logitsP[8][BATCH * 1024];    // split-K partials
__device__ int   g_feed[BATCH];
__device__ int   g_ended[BATCH];
__device__ unsigned g_cnt = 0, g_gen = 0;
__device__ uint4 g_WB[TOT_SLOTS];               // pre-fragmented split-bf16 weights
// A in mma-fragment layout: per 64-K chunk = 8192 uints (hi plane 4096 | lo plane 4096)
__device__ uint g_hf[2][2][2][16 * 8192];       // [layer][dir][buf], 16 chunks
__device__ uint g_whf[32 * 8192];               // scrambled fc input, 32 chunks

// ---------------- helpers ----------------------------------------------------
__device__ __forceinline__ uint prmt(uint a, uint b, uint s) {
    uint r; asm("prmt.b32 %0, %1, %2, %3;" : "=r"(r) : "r"(a), "r"(b), "r"(s));
    return r;
}
__device__ __forceinline__ uint b2u(__nv_bfloat162 v) { return *reinterpret_cast<uint*>(&v); }
__device__ __forceinline__ uint pack_split(float v) {
    __nv_bfloat16 h = __float2bfloat16_rn(v);
    float hf = __bfloat162float(h);
    __nv_bfloat16 l = __float2bfloat16_rn(v - hf);
    return (uint)__bfloat16_as_ushort(h) | ((uint)__bfloat16_as_ushort(l) << 16);
}
__device__ __forceinline__ float sigf(float x) { return 1.0f / (1.0f + expf(-x)); }
__device__ __forceinline__ uint s2u(const void* p) {
    uint a;
    asm("{ .reg .u64 t; cvta.to.shared.u64 t, %1; cvt.u32.u64 %0, t; }" : "=r"(a) : "l"(p));
    return a;
}
// fragment slot for value pair (b-row, even j): uint index within an 8192-uint chunk
__device__ __forceinline__ int frag_slot(int brow, int j) {
    int kl = (j >> 4) & 3, pk = (j >> 1) & 7;
    return ((kl * 8 + (brow >> 4)) * 32 + (brow & 7) * 4 + (pk & 3)) * 4
           + ((brow >> 3) & 1) + 2 * (pk >> 2);
}

#define MMA_OP(d, a, bb0, bb1) \
    asm volatile( \
        "mma.sync.aligned.m16n8k16.row.col.f32.bf16.bf16.f32 " \
        "{%0,%1,%2,%3}, {%4,%5,%6,%7}, {%8,%9}, {%0,%1,%2,%3};" \
        : "+f"((d)[0]), "+f"((d)[1]), "+f"((d)[2]), "+f"((d)[3]) \
        : "r"((a)[0]), "r"((a)[1]), "r"((a)[2]), "r"((a)[3]), "r"(bb0), "r"(bb1))

#define CP_ASYNC16(daddr, saddr) \
    asm volatile("cp.async.cg.shared.global [%0], [%1], 16;" :: "r"(daddr), "l"(saddr) : "memory")
#define CP_COMMIT() asm volatile("cp.async.commit_group;" ::: "memory")
#define CP_WAIT2()  asm volatile("cp.async.wait_group 2;" ::: "memory")
#define CP_WAIT1()  asm volatile("cp.async.wait_group 1;" ::: "memory")
#define CP_WAIT0()  asm volatile("cp.async.wait_group 0;" ::: "memory")

// ---------------- f32x2 helpers (pcomp only) --------------------------------
__device__ __forceinline__ ull pk2(float lo, float hi) {
    ull r; asm("mov.b64 %0, {%1,%2};" : "=l"(r) : "f"(lo), "f"(hi)); return r;
}
__device__ __forceinline__ void fma2(ull& d, ull a, ull b) {
    asm("fma.rn.f32x2 %0, %1, %2, %0;" : "+l"(d) : "l"(a), "l"(b));
}
__device__ __forceinline__ float2 unpk(ull v) {
    float2 r; asm("mov.b64 {%0,%1}, %2;" : "=f"(r.x), "=f"(r.y) : "l"(v)); return r;
}

// ---------------- software grid barrier --------------------------------------
__device__ __forceinline__ void gbar() {
    __threadfence();
    __syncthreads();
    if (threadIdx.x == 0) {
        unsigned gen = atomicAdd(&g_gen, 0u);
        unsigned arrived = atomicAdd(&g_cnt, 1u);
        if (arrived == NBLK - 1u) {
            atomicExch(&g_cnt, 0u);
            __threadfence();
            atomicAdd(&g_gen, 1u);
        } else {
            while (atomicAdd(&g_gen, 0u) == gen) { __nanosleep(64); }
        }
        __threadfence();
    }
    __syncthreads();
}

// ---------------- init: h fragments + c + feed --------------------------------
__device__ void init_phase(int bid, const int* __restrict__ yy,
                           const float* __restrict__ h_t,
                           const float* __restrict__ h_tr,
                           const float* __restrict__ c0,
                           const float* __restrict__ c0r) {
    const int gid0 = bid * NTHR + threadIdx.x;
    const int LBH = BATCH * 1024;
    // h -> fragment layout, buffer 0
    for (int i = gid0; i < 2 * 2 * 128 * 512; i += NBLK * NTHR) {
        int l = i >> 17;
        int rem = i & 131071;
        int dr = rem >> 16;
        int rem2 = rem & 65535;
        int b = rem2 >> 9;
        int pj = rem2 & 511;
        int j = pj * 2;
        const float* src = (dr ? h_tr : h_t) + (size_t)l * LBH + b * 1024 + j;
        uint ps0 = pack_split(src[0]);
        uint ps1 = pack_split(src[1]);
        uint hiU = prmt(ps0, ps1, 0x5410), loU = prmt(ps0, ps1, 0x7632);
        int cch = j >> 6;
        int slot = frag_slot(b, j);
        uint* hf = &g_hf[l][dr][0][0];
        hf[cch * 8192 + slot] = hiU;
        hf[cch * 8192 + 4096 + slot] = loU;
    }
    for (int i = gid0; i < 2 * LBH; i += NBLK * NTHR) {
        int l = i / LBH, r = i % LBH, j = r & 1023;
        g_c[l][0][r] = c0[l * 1024 + j];
        g_c[l][1][r] = c0r[l * 1024 + j];
    }
    if (bid == 0 && threadIdx.x < BATCH) {
        g_feed[threadIdx.x] = yy[threadIdx.x * TSTEPS];
        g_ended[threadIdx.x] = 0;
    }
}

// ---------------- setup: split + pre-fragment weights ------------------------
__device__ void setup_weights(int bid,
    const float* __restrict__ W_ih, const float* __restrict__ W_hh,
    const float* __restrict__ W_ihr, const float* __restrict__ W_hhr,
    const float* __restrict__ fcW) {
    for (uint s = bid * NTHR + threadIdx.x; s < TOT_SLOTS; s += NBLK * NTHR) {
        const float* p;
        if (s < CELL_SLOTS) {
            uint tile = s >> 14, rem = s & 16383u;
            uint ks = rem >> 8, nf = (rem >> 5) & 7, lane = rem & 31;
            uint dir = tile / 192, seg = (tile / 64) % 3, jt = tile & 63;
            const float* W;
            if (seg == 0)      W = dir ? W_hhr : W_hh;
            else if (seg == 1) W = (dir ? W_ihr : W_ih) + (size_t)4096 * 1024;
            else               W = (dir ? W_hhr : W_hh) + (size_t)4096 * 1024;
            uint n = nf * 8 + (lane >> 2);
            uint row = (n >> 4) * 1024 + jt * 16 + (n & 15);
            uint kb = ks * 16 + (lane & 3) * 2;
            p = W + (size_t)row * 1024 + kb;
        } else {
            uint srel = s - CELL_SLOTS;
            uint f = srel >> 12, rem = srel & 4095u;
            uint ks = rem >> 8, nf = (rem >> 5) & 7, lane = rem & 31;
            uint et = f >> 3, ks2 = f & 7;
            uint n = nf * 8 + (lane >> 2);
            uint row = et * 64 + n;
            uint kb = ks2 * 256 + ks * 16 + (lane & 3) * 2;
            p = fcW + (size_t)row * 2048 + kb;
        }
        float2 r01 = __ldg((const float2*)p);
        float2 r89 = __ldg((const float2*)(p + 8));
        __nv_bfloat162 H01 = __floats2bfloat162_rn(r01.x, r01.y);
        __nv_bfloat162 H89 = __floats2bfloat162_rn(r89.x, r89.y);
        __nv_bfloat162 L01 = __floats2bfloat162_rn(r01.x - __bfloat162float(H01.x),
                                                   r01.y - __bfloat162float(H01.y));
        __nv_bfloat162 L89 = __floats2bfloat162_rn(r89.x - __bfloat162float(H89.x),
                                                   r89.y - __bfloat162float(H89.y));
        g_WB[s] = make_uint4(b2u(H01), b2u(H89), b2u(L01), b2u(L89));
    }
}

// ---------------- pcomp (fp32 f32x2, 512 thr): P = emb @ W_ih(l0)^T ----------
__device__ void pcomp_phase(char* dsm, int bid, const float* __restrict__ emb,
                            const float* __restrict__ W_ih,
                            const float* __restrict__ W_ihr) {
    float (*As)[16][132] = (float(*)[16][132])(dsm);
    float (*Bs)[16][68]  = (float(*)[16][68])(dsm + 2 * 16 * 132 * 4);
    const int tid = threadIdx.x;
    const int ty = tid >> 4, tx = tid & 15;
    const int m0 = ty << 2, n0 = tx << 2;
    const int ar = tid >> 2, q4 = (tid & 3) << 2;
    const bool bload = (tid < 256);
    const int br = tid >> 2;

    for (int it = 0; it < 8; ++it) {
        int tile = bid + (it << 7);
        int dir = tile >> 9, mt = (tile >> 6) & 7, nt = tile & 63;
        const float* Bw = dir ? W_ihr : W_ih;
        const int m0g = mt << 7, n0g = nt << 6;
        const float* arow = emb + (size_t)(m0g + ar) * 1024 + q4;
        const float* brow = Bw + (size_t)(n0g + br) * 1024 + q4;

        ull acc[2][4];
#pragma unroll
        for (int i = 0; i < 2; i++)
#pragma unroll
            for (int j = 0; j < 4; j++) acc[i][j] = 0ULL;

        float4 pa = __ldg((const float4*)arow);
        float4 pb = make_float4(0.f, 0.f, 0.f, 0.f);
        if (bload) pb = __ldg((const float4*)brow);
        int cur = 0;
        {
            float (*A)[132] = As[0]; float (*B)[68] = Bs[0];
            A[q4+0][ar]=pa.x; A[q4+1][ar]=pa.y; A[q4+2][ar]=pa.z; A[q4+3][ar]=pa.w;
            if (bload) { B[q4+0][br]=pb.x; B[q4+1][br]=pb.y; B[q4+2][br]=pb.z; B[q4+3][br]=pb.w; }
        }
        __syncthreads();
        for (int kk = 0; kk < 64; ++kk) {
            const bool more = (kk + 1) < 64;
            if (more) {
                int k0 = (kk + 1) << 4;
                pa = __ldg((const float4*)(arow + k0));
                if (bload) pb = __ldg((const float4*)(brow + k0));
            }
            {
                const float (*A)[132] = As[cur]; const float (*B)[68] = Bs[cur];
#pragma unroll
                for (int k = 0; k < 16; k++) {
                    const ull* ap = (const ull*)&A[k][m0];
                    ull a0 = ap[0], a1 = ap[1];
                    float4 bv = *(const float4*)&B[k][n0];
                    ull p0=pk2(bv.x,bv.x), p1=pk2(bv.y,bv.y), p2=pk2(bv.z,bv.z), p3=pk2(bv.w,bv.w);
                    fma2(acc[0][0],a0,p0); fma2(acc[0][1],a0,p1); fma2(acc[0][2],a0,p2); fma2(acc[0][3],a0,p3);
                    fma2(acc[1][0],a1,p0); fma2(acc[1][1],a1,p1); fma2(acc[1][2],a1,p2); fma2(acc[1][3],a1,p3);
                }
            }
            if (more) {
                float (*A)[132] = As[cur^1]; float (*B)[68] = Bs[cur^1];
                A[q4+0][ar]=pa.x; A[q4+1][ar]=pa.y; A[q4+2][ar]=pa.z; A[q4+3][ar]=pa.w;
                if (bload) { B[q4+0][br]=pb.x; B[q4+1][br]=pb.y; B[q4+2][br]=pb.z; B[q4+3][br]=pb.w; }
                __syncthreads();
                cur ^= 1;
            }
        }
        __syncthreads();
#pragma unroll
        for (int mp = 0; mp < 2; mp++) {
            int m = m0g + m0 + (mp << 1);
#pragma unroll
            for (int j = 0; j < 4; j++) {
                float2 v = unpk(acc[mp][j]);
                g_P[dir][m][n0g + n0 + j] = v.x;
                g_P[dir][m + 1][n0g + n0 + j] = v.y;
            }
        }
        __syncthreads();
    }
}

// ---------------- HMMA GEMM core: fragment-direct A, 4-buffer B stream -------
// zs[128][66] = A[128, K] @ W^T tile (64 n); A read as pre-built mma fragments
// (one uint4 LDG per plane per warp per k16); B streamed via cp.async into 4
// smem buffers, issue-early (prefetch distance 2, race-free by sync fencing).
__device__ __noinline__ void gemm_mma(char* dsm, uint smbB, float (*zs)[66],
    const uint* __restrict__ Af0, const uint* __restrict__ Af1,
    int nch, int nch0,
    const uint4* __restrict__ tb0, const uint4* __restrict__ tb1) {
    const int tid = threadIdx.x;
    const int lane = tid & 31, wid = tid >> 5;
    const int wn = wid & 1, wm = wid >> 1;
    const int lq = lane >> 2, lr = lane & 3;
    uint4* smB = (uint4*)dsm;
    const uint alin = wm * 128 + lane * 4;

    float acc[4][4];
#pragma unroll
    for (int f = 0; f < 4; f++)
#pragma unroll
        for (int k = 0; k < 4; k++) acc[f][k] = 0.0f;

    // B prologue: chunks 0, 1 into buffers 0, 1
    {
        const uint4* s = tb0 + tid;
        CP_ASYNC16(smbB + tid * 16, s);
        CP_ASYNC16(smbB + tid * 16 + 8192, s + 512);
        CP_COMMIT();
    }
    if (nch > 1) {
        int sg = (1 >= nch0);
        const uint4* s = (sg ? tb1 : tb0) + (size_t)(1 - (sg ? nch0 : 0)) * 1024 + tid;
        CP_ASYNC16(smbB + 16384 + tid * 16, s);
        CP_ASYNC16(smbB + 16384 + tid * 16 + 8192, s + 512);
        CP_COMMIT();
    }
    // A prologue: (c=0, kl=0)
    uint4 cah = __ldcg((const uint4*)(Af0 + alin));
    uint4 cal = __ldcg((const uint4*)(Af0 + 4096 + alin));

    for (int c = 0; c < nch; ++c) {
        // issue B(c+2) EARLY into buffer (c+2)&3 (last read at chunk c-2; fenced
        // by the __syncthreads of iteration c-1 -> race-free)
        if (c + 2 < nch) {
            int cn = c + 2, sg = (cn >= nch0);
            const uint4* s = (sg ? tb1 : tb0) + (size_t)(cn - (sg ? nch0 : 0)) * 1024 + tid;
            uint d = smbB + (cn & 3) * 16384 + tid * 16;
            CP_ASYNC16(d, s);
            CP_ASYNC16(d + 8192, s + 512);
            CP_COMMIT();
            CP_WAIT2();
        } else if (c + 1 < nch) {
            CP_WAIT1();
        } else {
            CP_WAIT0();
        }
        __syncthreads();

        const uint4* Bb = smB + (c & 3) * 1024;
#pragma unroll
        for (int kl = 0; kl < 4; kl++) {
            uint4 nah, nal;
            const bool hasnext = !((kl == 3) && (c + 1 == nch));
            if (hasnext) {
                int nc = (kl == 3) ? c + 1 : c;
                int nkl = (kl == 3) ? 0 : kl + 1;
                int sg = (nc >= nch0);
                const uint* Afs = (sg ? Af1 : Af0) + (size_t)(nc - (sg ? nch0 : 0)) * 8192;
                nah = __ldcg((const uint4*)(Afs + nkl * 1024 + alin));
                nal = __ldcg((const uint4*)(Afs + 4096 + nkl * 1024 + alin));
            } else {
                nah = cah; nal = cal;
            }
            const uint4* bp = Bb + (kl * 8 + wn * 4) * 32 + lane;
            uint4 B0 = bp[0], B1 = bp[32], B2 = bp[64], B3 = bp[96];
            const uint* ah = (const uint*)&cah;
            const uint* al = (const uint*)&cal;
            MMA_OP(acc[0], ah, B0.x, B0.y); MMA_OP(acc[1], ah, B1.x, B1.y);
            MMA_OP(acc[2], ah, B2.x, B2.y); MMA_OP(acc[3], ah, B3.x, B3.y);
            MMA_OP(acc[0], ah, B0.z, B0.w); MMA_OP(acc[1], ah, B1.z, B1.w);
            MMA_OP(acc[2], ah, B2.z, B2.w); MMA_OP(acc[3], ah, B3.z, B3.w);
            MMA_OP(acc[0], al, B0.x, B0.y); MMA_OP(acc[1], al, B1.x, B1.y);
            MMA_OP(acc[2], al, B2.x, B2.y); MMA_OP(acc[3], al, B3.x, B3.y);
            cah = nah; cal = nal;
        }
    }

    // accumulators -> zs
#pragma unroll
    for (int f = 0; f < 4; f++) {
        int m = wm * 16 + lq;
        int n = wn * 32 + f * 8 + lr * 2;
        *(float2*)&zs[m][n]     = make_float2(acc[f][0], acc[f][1]);
        *(float2*)&zs[m + 8][n] = make_float2(acc[f][2], acc[f][3]);
    }
    __syncthreads();
}

// ---------------- cell epilogue: gates + state + fragment writes --------------
__device__ void cell_epilogue(char* dsm, float (*zs)[66], int layer, int dir,
    int jt, int np, const float* __restrict__ bi, const float* __restrict__ bh,
    uint* __restrict__ hfout, bool dowh) {
    const int tid = threadIdx.x;
    const int j0 = jt << 4;
    uint* hs = (uint*)(dsm + HS_OFF);   // [16][132]
    const int cch = jt >> 2, kl = jt & 3;

#pragma unroll
    for (int it = 0; it < 2; ++it) {
        int item = tid + (it << 9);       // 0..1023
        int b = item >> 3, pk = item & 7;
        int jj0 = pk * 2, jj1 = jj0 + 1;
        int jg0 = j0 + jj0, jg1 = j0 + jj1;
        float z0[4], z1[4];
        z0[0] = zs[b][jj0]      + bi[jg0]        + bh[jg0];
        z0[1] = zs[b][16 + jj0] + bi[1024 + jg0] + bh[1024 + jg0];
        z0[2] = zs[b][32 + jj0] + bi[2048 + jg0] + bh[2048 + jg0];
        z0[3] = zs[b][48 + jj0] + bi[3072 + jg0] + bh[3072 + jg0];
        z1[0] = zs[b][jj1]      + bi[jg1]        + bh[jg1];
        z1[1] = zs[b][16 + jj1] + bi[1024 + jg1] + bh[1024 + jg1];
        z1[2] = zs[b][32 + jj1] + bi[2048 + jg1] + bh[2048 + jg1];
        z1[3] = zs[b][48 + jj1] + bi[3072 + jg1] + bh[3072 + jg1];
        if (layer == 0) {
            int feed = __ldcg(&g_feed[b]);
            const float* pr = &g_P[dir][feed][0];
            z0[0] += pr[jg0]; z0[1] += pr[1024 + jg0]; z0[2] += pr[2048 + jg0]; z0[3] += pr[3072 + jg0];
            z1[0] += pr[jg1]; z1[1] += pr[1024 + jg1]; z1[2] += pr[2048 + jg1]; z1[3] += pr[3072 + jg1];
        }
        uint ps0, ps1;
        {
            float ig = sigf(z0[0]), fg = sigf(z0[1]), gv = tanhf(z0[2]), og = sigf(z0[3]);
            int idx = b * 1024 + jg0;
            float cn = fg * g_c[layer][dir][idx] + ig * gv;
            float hn = og * tanhf(cn);
            g_c[layer][dir][idx] = cn;
            ps0 = pack_split(hn);
        }
        {
            float ig = sigf(z1[0]), fg = sigf(z1[1]), gv = tanhf(z1[2]), og = sigf(z1[3]);
            int idx = b * 1024 + jg1;
            float cn = fg * g_c[layer][dir][idx] + ig * gv;
            float hn = og * tanhf(cn);
            g_c[layer][dir][idx] = cn;
            ps1 = pack_split(hn);
        }
        uint hiU = prmt(ps0, ps1, 0x5410);
        uint loU = prmt(ps0, ps1, 0x7632);
        int slot = ((kl * 8 + (b >> 4)) * 32 + (b & 7) * 4 + (pk & 3)) * 4
                   + ((b >> 3) & 1) + 2 * (pk >> 2);
        hfout[cch * 8192 + slot] = hiU;
        hfout[cch * 8192 + 4096 + slot] = loU;
        if (dowh) {
            hs[jj0 * 132 + b] = ps0;
            hs[jj1 * 132 + b] = ps1;
        }
    }
    if (dowh) {
        __syncthreads();
#pragma unroll
        for (int it = 0; it < 2; ++it) {
            int item = tid + (it << 9);
            int ccl = item >> 6, bp = item & 63;
            int b0 = bp * 2, b1 = b0 + 1;
            uint psa = hs[ccl * 132 + b0], psb = hs[ccl * 132 + b1];
            uint hiU = prmt(psa, psb, 0x5410), loU = prmt(psa, psb, 0x7632);
            int cc = (dir << 10) + (jt << 4) + ccl;
            int b2 = cc >> 4;
            int j2 = ((cc & 15) << 7) + b0;   // even
            int c2 = j2 >> 6;
            int slot = frag_slot(b2, j2);
            g_whf[c2 * 8192 + slot] = hiU;
            g_whf[c2 * 8192 + 4096 + slot] = loU;
        }
    }
}

// ---------------- fc epilogue --------------------------------------------------
__device__ __forceinline__ void fc_epilogue(float (*zs)[66], int et, int ks2) {
    const int tid = threadIdx.x;
    const int b = tid >> 2, n0 = (tid & 3) << 4;
    float* lp = &g_logitsP[ks2][b * 1024 + et * 64 + n0];
#pragma unroll
    for (int j = 0; j < 16; j++) lp[j] = zs[b][n0 + j];
}

// ---------------- final phase --------------------------------------------------
__device__ void final_phase(char* dsm, int bid, const float* __restrict__ fc_b,
                            float* __restrict__ out, int t) {
    const int b = bid;
    const int tid = threadIdx.x;
    float* sl = (float*)(dsm + ZS_OFF);
    float* sv = sl + 1024;
    int*   si = (int*)(sl + 1536);
    float* ssum = sl + 2048;

    const int end = __ldcg(&g_ended[b]);
    float bv = -3.402823466e38f;
    int bidx = 0;
    for (int e = tid; e < 1024; e += NTHR) {
        float v;
        if (end) {
            v = (e == 1) ? 1.0f : 0.0f;
        } else {
            v = fc_b[e];
#pragma unroll
            for (int s = 0; s < 8; s++) v += __ldcg(&g_logitsP[s][b * 1024 + e]);
        }
        sl[e] = v;
        if (v > bv) { bv = v; bidx = e; }
    }
    sv[tid] = bv; si[tid] = bidx;
    __syncthreads();
    for (int s = NTHR / 2; s > 0; s >>= 1) {
        if (tid < s) {
            float v2 = sv[tid + s]; int i2 = si[tid + s];
            if (v2 > sv[tid] || (v2 == sv[tid] && i2 < si[tid])) { sv[tid] = v2; si[tid] = i2; }
        }
        __syncthreads();
    }
    float mx = sv[0];
    int label = si[0];
    __syncthreads();

    float ps = 0.0f;
    for (int e = tid; e < 1024; e += NTHR) ps += expf(sl[e] - mx);
    ssum[tid] = ps;
    __syncthreads();
    for (int s = NTHR / 2; s > 0; s >>= 1) {
        if (tid < s) ssum[tid] += ssum[tid + s];
        __syncthreads();
    }
    float inv = 1.0f / ssum[0];

    float* orow = out + ((size_t)b * TSTEPS + t) * 1024;
    for (int e = tid; e < 1024; e += NTHR) orow[e] = expf(sl[e] - mx) * inv;

    if (tid == 0) {
        g_feed[b] = label;
        g_ended[b] = end | (label == 1);  // EOS = 1
    }
}

// ---------------- mega kernel --------------------------------------------------
__global__ void __launch_bounds__(NTHR, 1) main_kernel(
    const int* __restrict__ yy,
    const float* __restrict__ h_t, const float* __restrict__ h_tr,
    const float* __restrict__ c0, const float* __restrict__ c0r,
    const float* __restrict__ emb,
    const float* __restrict__ W_ih, const float* __restrict__ W_hh,
    const float* __restrict__ b_ih, const float* __restrict__ b_hh,
    const float* __restrict__ W_ihr, const float* __restrict__ W_hhr,
    const float* __restrict__ b_ihr, const float* __restrict__ b_hhr,
    const float* __restrict__ fcW, const float* __restrict__ fc_b,
    float* __restrict__ out) {
    extern __shared__ char dsm[];
    const uint smbB = s2u(dsm);
    float (*zs)[66] = (float(*)[66])(dsm + ZS_OFF);
    const int bid = blockIdx.x;

    init_phase(bid, yy, h_t, h_tr, c0, c0r);
    setup_weights(bid, W_ih, W_hh, W_ihr, W_hhr, fcW);
    pcomp_phase(dsm, bid, emb, W_ih, W_ihr);
    gbar();

    const int dir = bid >> 6;
    const int jt = bid & 63;
    const int et = bid >> 3;
    const int ks2 = bid & 7;
    const float* bi0 = (dir ? b_ihr : b_ih);
    const float* bh0 = (dir ? b_hhr : b_hh);
    const float* bi1 = bi0 + 4096;
    const float* bh1 = bh0 + 4096;
    const uint4* tL0  = g_WB + (size_t)((dir * 3 + 0) * 64 + jt) * 16384;
    const uint4* tL1a = g_WB + (size_t)((dir * 3 + 1) * 64 + jt) * 16384;
    const uint4* tL1b = g_WB + (size_t)((dir * 3 + 2) * 64 + jt) * 16384;
    const uint4* tFC  = g_WB + CELL_SLOTS + (size_t)(et * 8 + ks2) * 4096;

    for (int t = 0; t < TSTEPS; ++t) {
        const int p = t & 1;
        const int np = p ^ 1;
        // layer 0: z = h0_prev @ Whh0^T (+ P[feed] in epilogue)
        gemm_mma(dsm, smbB, zs, g_hf[0][dir][p], g_hf[0][dir][p], 16, 16, tL0, tL0);
        cell_epilogue(dsm, zs, 0, dir, jt, np, bi0, bh0, g_hf[0][dir][np], false);
        gbar();
        // layer 1: z = h0_new @ Wih1^T + h1_prev @ Whh1^T
        gemm_mma(dsm, smbB, zs, g_hf[0][dir][np], g_hf[1][dir][p], 32, 16, tL1a, tL1b);
        cell_epilogue(dsm, zs, 1, dir, jt, np, bi1, bh1, g_hf[1][dir][np], true);
        gbar();
        // fc: logits partial, K slice ks2*256..+256 (wh fragment chunks ks2*4..+4)
        gemm_mma(dsm, smbB, zs, g_whf + (size_t)(ks2 * 4) * 8192,
                 g_whf, 4, 4, tFC, tFC);
        fc_epilogue(zs, et, ks2);
        gbar();
        final_phase(dsm, bid, fc_b, out, t);
        gbar();
    }
}

// ---------------- launch --------------------------------------------------------
extern "C" void kernel_launch(void* const* d_in, const int* in_sizes, int n_in,
                              void* d_out, int out_size) {
    const int* yy = (const int*)d_in[0];
    const float* h_t = (const float*)d_in[1];
    const float* h_tr = (const float*)d_in[2];
    // d_in[3] = x_lens (unused by the reference computation)
    const float* emb = (const float*)d_in[4];
    const float* W_ih = (const float*)d_in[5];
    const float* W_hh = (const float*)d_in[6];
    const float* b_ih = (const float*)d_in[7];
    const float* b_hh = (const float*)d_in[8];
    const float* W_ihr = (const float*)d_in[9];
    const float* W_hhr = (const float*)d_in[10];
    const float* b_ihr = (const float*)d_in[11];
    const float* b_hhr = (const float*)d_in[12];
    const float* c0 = (const float*)d_in[13];
    const float* c0r = (const float*)d_in[14];
    const float* fc_W = (const float*)d_in[15];
    const float* fc_b = (const float*)d_in[16];
    float* out = (float*)d_out;

    cudaFuncSetAttribute(main_kernel, cudaFuncAttributeMaxDynamicSharedMemorySize, SMEM_BYTES);
    main_kernel<<<NBLK, NTHR, SMEM_BYTES>>>(yy, h_t, h_tr, c0, c0r, emb,
                                            W_ih, W_hh, b_ih, b_hh,
                                            W_ihr, W_hhr, b_ihr, b_hhr,
                                            fc_W, fc_b, out);
}